// round 14
// baseline (speedup 1.0000x reference)
#include <cuda_runtime.h>
#include <cuda_fp16.h>
#include <cstdint>

#define NB 32
#define NS 2048
#define DE 1024
#define NU 1024

// ---------------- scratch (static device arrays; no runtime allocation) ----------------
__device__ float g_dp[NB * NU];                 // dec_proj + b1 (exact fp32)
__device__ float g_e2[NB * NS];                 // energies2 pre-softmax
__device__ float g_cpart[16 * NB * DE];         // context partials
__device__ __half g_w1t[NU * DE];               // W1enc^T fp16 [u][k]
__device__ __half g_ah[(size_t)NB * NS * DE];   // henc fp16 [row][k]
__device__ int g_ctr[NB];                       // arrival counters (reset to 0 each launch)

// ---------------- helpers ----------------
__device__ __forceinline__ uint32_t smem_u32(const void* p) {
    uint32_t a;
    asm("{ .reg .u64 t; cvta.to.shared.u64 t, %1; cvt.u32.u64 %0, t; }" : "=r"(a) : "l"(p));
    return a;
}
#define SWZ(x) ((x) ^ (((x) >> 3) & 0x70))

__device__ __forceinline__ void cpa16(uint32_t dst, const void* src) {
    asm volatile("cp.async.cg.shared.global [%0], [%1], 16;" :: "r"(dst), "l"(src));
}
__device__ __forceinline__ void ldsm4(uint32_t* r, uint32_t addr) {
    asm volatile("ldmatrix.sync.aligned.m8n8.x4.shared.b16 {%0,%1,%2,%3}, [%4];"
                 : "=r"(r[0]), "=r"(r[1]), "=r"(r[2]), "=r"(r[3]) : "r"(addr));
}
__device__ __forceinline__ void mma16816(float* c, const uint32_t* a, uint32_t b0, uint32_t b1) {
    asm volatile(
        "mma.sync.aligned.m16n8k16.row.col.f32.f16.f16.f32 "
        "{%0,%1,%2,%3}, {%4,%5,%6,%7}, {%8,%9}, {%0,%1,%2,%3};"
        : "+f"(c[0]), "+f"(c[1]), "+f"(c[2]), "+f"(c[3])
        : "r"(a[0]), "r"(a[1]), "r"(a[2]), "r"(a[3]), "r"(b0), "r"(b1));
}
__device__ __forceinline__ float tanh_fast(float x) {
    float t;
    asm("tanh.approx.f32 %0, %1;" : "=f"(t) : "f"(x));
    return t;
}

// ---------------- Kernel P: w1split | decproj | asplit merged (disjoint block ranges) ----------
// Short blocks first; asplit blocks each process 1024 float4 (4 per thread, MLP=4).
#define PREP_W1_BLOCKS 1024                       // 32 kblk x 32 ublk
#define PREP_DEC_BLOCKS 128                       // 4 uchunk x 32 b
#define PREP_SHORT (PREP_W1_BLOCKS + PREP_DEC_BLOCKS)
#define PREP_ASPLIT_BLOCKS 16384                  // 16M float4 / 1024
#define PREP_BLOCKS (PREP_SHORT + PREP_ASPLIT_BLOCKS)

__global__ __launch_bounds__(256) void k_prep(const float* __restrict__ henc,
                                              const float* __restrict__ W1,
                                              const float* __restrict__ hdec,
                                              const float* __restrict__ b1) {
    int bx = blockIdx.x, tid = threadIdx.x;
    if (bx < PREP_W1_BLOCKS) {
        // transpose W1enc into fp16 [u][k]
        __shared__ float t[32][33];
        int k0 = (bx & 31) * 32, u0 = (bx >> 5) * 32;
        int tx = tid & 31, ty = tid >> 5;  // 32x8
#pragma unroll
        for (int i = 0; i < 32; i += 8)
            t[ty + i][tx] = W1[(size_t)(k0 + ty + i) * NU + u0 + tx];
        __syncthreads();
#pragma unroll
        for (int i = 0; i < 32; i += 8) {
            float v = t[tx][ty + i];
            g_w1t[(size_t)(u0 + ty + i) * DE + k0 + tx] = __float2half_rn(v);
        }
    } else if (bx < PREP_SHORT) {
        // dec_proj (exact fp32)
        int b3x = bx - PREP_W1_BLOCKS;
        int b = b3x >> 2;
        int u = (b3x & 3) * 256 + tid;
        const float* hd = hdec + b * DE;
        float acc = b1[u];
#pragma unroll 8
        for (int k = 0; k < DE; k++)
            acc = fmaf(hd[k], W1[(size_t)(DE + k) * NU + u], acc);
        g_dp[b * NU + u] = acc;
    } else {
        // henc fp32 -> fp16, 4 independent float4s per thread (front-batched loads, MLP=4)
        size_t base = (size_t)(bx - PREP_SHORT) * 1024 + tid;
        float4 v[4];
#pragma unroll
        for (int q = 0; q < 4; q++) v[q] = ((const float4*)henc)[base + q * 256];
#pragma unroll
        for (int q = 0; q < 4; q++) {
            __half2 h0 = __floats2half2_rn(v[q].x, v[q].y);
            __half2 h1 = __floats2half2_rn(v[q].z, v[q].w);
            ((uint2*)g_ah)[base + q * 256] = make_uint2(*(uint32_t*)&h0, *(uint32_t*)&h1);
        }
    }
}

// ---------------- Kernel 2: fp16 mma fused energies — R8-proven, unchanged --------------------
#define STG_BYTES 32768
#define SM_DP (3 * STG_BYTES)          // 98304
#define SM_W2 (SM_DP + 4096)
#define SM_EBUF (SM_W2 + 4096)
#define SM_TOTAL (SM_EBUF + 2048)      // 108544

#define NSTG 128

__global__ __launch_bounds__(256, 2) void k_energies_mma(const float* __restrict__ W2,
                                                         const float* __restrict__ b2) {
    extern __shared__ char smem[];
    uint32_t sbase = smem_u32(smem);
    int tid = threadIdx.x, lane = tid & 31, wid = tid >> 5;
    int mwarp = wid >> 2, nwarp = wid & 3;  // 2 x 4
    int sblk = blockIdx.x, b = blockIdx.y;
    size_t rowbase = (size_t)b * NS + (size_t)sblk * 128;

    float* dp_s = (float*)(smem + SM_DP);
    float* w2_s = (float*)(smem + SM_W2);
    float* e2buf = (float*)(smem + SM_EBUF);
    for (int i = tid; i < NU; i += 256) {
        dp_s[i] = g_dp[b * NU + i];
        w2_s[i] = W2[i];
    }
    for (int i = tid; i < 512; i += 256) e2buf[i] = 0.f;
    __syncthreads();

    uint32_t a_off[4], b_off[2];
#pragma unroll
    for (int mf = 0; mf < 4; mf++) {
        int r = mwarp * 64 + mf * 16 + (lane & 15);
        int kb = (lane >> 4) * 16;
        a_off[mf] = SWZ((uint32_t)(r * 128 + kb));
    }
#pragma unroll
    for (int nf2 = 0; nf2 < 2; nf2++) {
        int n = nwarp * 32 + nf2 * 16 + ((lane >> 4) & 1) * 8 + (lane & 7);
        int kb = ((lane >> 3) & 1) * 16;
        b_off[nf2] = SWZ((uint32_t)(n * 128 + kb));
    }

    auto issue = [&](int fst) {
        int k0 = (fst & 15) << 6;
        int u0 = (fst >> 4) << 7;
        uint32_t sA = sbase + (uint32_t)(fst % 3) * STG_BYTES;
        uint32_t sB = sA + 16384;
#pragma unroll
        for (int i = 0; i < 4; i++) {
            int idx = i * 256 + tid;
            int r = idx >> 3, kc = idx & 7;
            cpa16(sA + SWZ((uint32_t)(r * 128 + kc * 16)),
                  g_ah + (rowbase + r) * DE + k0 + kc * 8);
        }
#pragma unroll
        for (int i = 0; i < 4; i++) {
            int idx = i * 256 + tid;
            int r = idx >> 3, kc = idx & 7;
            cpa16(sB + SWZ((uint32_t)(r * 128 + kc * 16)),
                  g_w1t + (size_t)(u0 + r) * DE + k0 + kc * 8);
        }
        asm volatile("cp.async.commit_group;" ::: "memory");
    };

    float acc[4][4][4];
#pragma unroll
    for (int mf = 0; mf < 4; mf++)
#pragma unroll
        for (int nf = 0; nf < 4; nf++)
#pragma unroll
            for (int j = 0; j < 4; j++) acc[mf][nf][j] = 0.f;

    issue(0);
    issue(1);
    for (int fst = 0; fst < NSTG; fst++) {
        if (fst + 1 < NSTG)
            asm volatile("cp.async.wait_group 1;" ::: "memory");
        else
            asm volatile("cp.async.wait_group 0;" ::: "memory");
        __syncthreads();

        uint32_t abase = sbase + (uint32_t)(fst % 3) * STG_BYTES;
        uint32_t bbase = abase + 16384;
#pragma unroll
        for (int kk = 0; kk < 4; kk++) {
            uint32_t a[4][4], bq[2][4];
#pragma unroll
            for (int mf = 0; mf < 4; mf++) ldsm4(a[mf], abase + (a_off[mf] ^ (kk << 5)));
#pragma unroll
            for (int nf2 = 0; nf2 < 2; nf2++) ldsm4(bq[nf2], bbase + (b_off[nf2] ^ (kk << 5)));
#pragma unroll
            for (int mf = 0; mf < 4; mf++)
#pragma unroll
                for (int nf = 0; nf < 4; nf++) {
                    int nf2 = nf >> 1, h = (nf & 1) * 2;
                    mma16816(acc[mf][nf], a[mf], bq[nf2][h], bq[nf2][h + 1]);
                }
        }
        if (fst + 2 < NSTG) issue(fst + 2);

        if ((fst & 15) == 15) {
            int u0 = (fst >> 4) << 7;
            float rowsum[4][2];
#pragma unroll
            for (int mf = 0; mf < 4; mf++) {
                rowsum[mf][0] = 0.f;
                rowsum[mf][1] = 0.f;
            }
#pragma unroll
            for (int mf = 0; mf < 4; mf++)
#pragma unroll
                for (int nf = 0; nf < 4; nf++)
#pragma unroll
                    for (int j = 0; j < 4; j++) {
                        int u = u0 + nwarp * 32 + nf * 8 + (lane & 3) * 2 + (j & 1);
                        float e1 = acc[mf][nf][j] + dp_s[u];
                        rowsum[mf][j >> 1] = fmaf(tanh_fast(e1), w2_s[u], rowsum[mf][j >> 1]);
                        acc[mf][nf][j] = 0.f;
                    }
#pragma unroll
            for (int mf = 0; mf < 4; mf++)
#pragma unroll
                for (int hh = 0; hh < 2; hh++) {
                    float v = rowsum[mf][hh];
                    v += __shfl_xor_sync(0xffffffffu, v, 1);
                    v += __shfl_xor_sync(0xffffffffu, v, 2);
                    if ((lane & 3) == 0) {
                        int row = mwarp * 64 + mf * 16 + (lane >> 2) + hh * 8;
                        e2buf[nwarp * 128 + row] += v;
                    }
                }
        }
    }
    __syncthreads();
    if (tid < 128) {
        float v = e2buf[tid] + e2buf[128 + tid] + e2buf[256 + tid] + e2buf[384 + tid] + b2[0];
        g_e2[b * NS + sblk * 128 + tid] = fmaxf(v, 0.f);
    }
}

// ---------------- Kernel 4: softmax + context partial + last-block reduce -----------------------
__global__ void k_ctxsoft(float* __restrict__ attn, float* __restrict__ ctx) {
    int sc = blockIdx.x, b = blockIdx.y, t = threadIdx.x;
    __shared__ float red[256];
    __shared__ float w[128];
    __shared__ int amLast;

    // --- softmax reduction (identical algorithm/order to the old k_softmax) ---
    float v[8];
    float mx = -1e30f;
#pragma unroll
    for (int q = 0; q < 8; q++) {
        v[q] = g_e2[b * NS + t + 256 * q];
        mx = fmaxf(mx, v[q]);
    }
    red[t] = mx;
    __syncthreads();
    for (int o = 128; o > 0; o >>= 1) {
        if (t < o) red[t] = fmaxf(red[t], red[t + o]);
        __syncthreads();
    }
    mx = red[0];
    __syncthreads();
    float s = 0.f;
#pragma unroll
    for (int q = 0; q < 8; q++) s += expf(v[q] - mx);
    red[t] = s;
    __syncthreads();
    for (int o = 128; o > 0; o >>= 1) {
        if (t < o) red[t] += red[t + o];
        __syncthreads();
    }
    float inv = 1.f / red[0];
    __syncthreads();

    if (t < 128) {
        float wv = expf(g_e2[b * NS + sc * 128 + t] - mx) * inv;
        w[t] = wv;
        attn[b * NS + sc * 128 + t] = wv;
    }
    __syncthreads();

    // --- context partial (fp16 henc) ---
    int d = t * 4;
    float4 acc = make_float4(0.f, 0.f, 0.f, 0.f);
    const __half* hp = g_ah + ((size_t)b * NS + (size_t)sc * 128) * DE + d;
#pragma unroll 4
    for (int s2 = 0; s2 < 128; s2++) {
        float ww = w[s2];
        uint2 hv = *(const uint2*)(hp + (size_t)s2 * DE);
        float2 f0 = __half22float2(*(const __half2*)&hv.x);
        float2 f1 = __half22float2(*(const __half2*)&hv.y);
        acc.x = fmaf(ww, f0.x, acc.x);
        acc.y = fmaf(ww, f0.y, acc.y);
        acc.z = fmaf(ww, f1.x, acc.z);
        acc.w = fmaf(ww, f1.y, acc.w);
    }
    *(float4*)&g_cpart[(size_t)(sc * NB + b) * DE + d] = acc;

    // --- last-block reduction: release (writer) AND acquire (reader) fences ---
    __threadfence();  // release: order this block's g_cpart stores before the RMW
    if (t == 0) {
        int old = atomicAdd(&g_ctr[b], 1);
        __threadfence();  // acquire for t0: order its later accesses after the RMW chain
        amLast = (old == 15);
    }
    __syncthreads();
    if (amLast) {
        __threadfence();  // acquire for t!=0 before reading other blocks' partials
#pragma unroll
        for (int rep = 0; rep < 4; rep++) {
            int dd = rep * 256 + t;
            float sum = 0.f;
#pragma unroll
            for (int scc = 0; scc < 16; scc++) sum += g_cpart[(size_t)(scc * NB + b) * DE + dd];
            ctx[b * DE + dd] = sum;
        }
        if (t == 0) g_ctr[b] = 0;  // reset for next graph replay
    }
}

extern "C" void kernel_launch(void* const* d_in, const int* in_sizes, int n_in,
                              void* d_out, int out_size) {
    const float* henc = (const float*)d_in[0];
    const float* hdec = (const float*)d_in[1];
    const float* W1 = (const float*)d_in[2];
    const float* b1 = (const float*)d_in[3];
    const float* W2 = (const float*)d_in[4];
    const float* b2 = (const float*)d_in[5];
    float* out = (float*)d_out;
    float* ctx = out;             // [32,1024]
    float* attn = out + NB * DE;  // [32,2048,1]

    cudaFuncSetAttribute(k_energies_mma, cudaFuncAttributeMaxDynamicSharedMemorySize, SM_TOTAL);

    k_prep<<<PREP_BLOCKS, 256>>>(henc, W1, hdec, b1);
    k_energies_mma<<<dim3(16, NB), 256, SM_TOTAL>>>(W2, b2);
    k_ctxsoft<<<dim3(16, NB), 256>>>(attn, ctx);
}

// round 15
// speedup vs baseline: 1.0300x; 1.0300x over previous
#include <cuda_runtime.h>
#include <cuda_fp16.h>
#include <cstdint>

#define NB 32
#define NS 2048
#define DE 1024
#define NU 1024

// ---------------- scratch (static device arrays; no runtime allocation) ----------------
__device__ float g_dp[NB * NU];                 // dec_proj + b1 (exact fp32)
__device__ float g_e2[NB * NS];                 // energies2 pre-softmax
__device__ float g_cpart[16 * NB * DE];         // context partials
__device__ __half g_w1t[NU * DE];               // W1enc^T fp16 [u][k]
__device__ __half g_ah[(size_t)NB * NS * DE];   // henc fp16 [row][k]
__device__ int g_ctr[NB];                       // arrival counters (reset to 0 each launch)

// ---------------- helpers ----------------
__device__ __forceinline__ uint32_t smem_u32(const void* p) {
    uint32_t a;
    asm("{ .reg .u64 t; cvta.to.shared.u64 t, %1; cvt.u32.u64 %0, t; }" : "=r"(a) : "l"(p));
    return a;
}
#define SWZ(x) ((x) ^ (((x) >> 3) & 0x70))

__device__ __forceinline__ void cpa16(uint32_t dst, const void* src) {
    asm volatile("cp.async.cg.shared.global [%0], [%1], 16;" :: "r"(dst), "l"(src));
}
__device__ __forceinline__ void ldsm4(uint32_t* r, uint32_t addr) {
    asm volatile("ldmatrix.sync.aligned.m8n8.x4.shared.b16 {%0,%1,%2,%3}, [%4];"
                 : "=r"(r[0]), "=r"(r[1]), "=r"(r[2]), "=r"(r[3]) : "r"(addr));
}
__device__ __forceinline__ void mma16816(float* c, const uint32_t* a, uint32_t b0, uint32_t b1) {
    asm volatile(
        "mma.sync.aligned.m16n8k16.row.col.f32.f16.f16.f32 "
        "{%0,%1,%2,%3}, {%4,%5,%6,%7}, {%8,%9}, {%0,%1,%2,%3};"
        : "+f"(c[0]), "+f"(c[1]), "+f"(c[2]), "+f"(c[3])
        : "r"(a[0]), "r"(a[1]), "r"(a[2]), "r"(a[3]), "r"(b0), "r"(b1));
}
__device__ __forceinline__ float tanh_fast(float x) {
    float t;
    asm("tanh.approx.f32 %0, %1;" : "=f"(t) : "f"(x));
    return t;
}

// ---------------- Kernel P: w1split | decproj | asplit merged (disjoint block ranges) ----------
// Short blocks first; asplit back to R12 shape (1 float4/thread, max warp-parallelism).
#define PREP_W1_BLOCKS 1024                       // 32 kblk x 32 ublk
#define PREP_DEC_BLOCKS 128                       // 4 uchunk x 32 b
#define PREP_SHORT (PREP_W1_BLOCKS + PREP_DEC_BLOCKS)
#define PREP_ASPLIT_BLOCKS 65536                  // 16M float4 / 256
#define PREP_BLOCKS (PREP_SHORT + PREP_ASPLIT_BLOCKS)

__global__ __launch_bounds__(256) void k_prep(const float* __restrict__ henc,
                                              const float* __restrict__ W1,
                                              const float* __restrict__ hdec,
                                              const float* __restrict__ b1) {
    int bx = blockIdx.x, tid = threadIdx.x;
    if (bx < PREP_W1_BLOCKS) {
        // transpose W1enc into fp16 [u][k]
        __shared__ float t[32][33];
        int k0 = (bx & 31) * 32, u0 = (bx >> 5) * 32;
        int tx = tid & 31, ty = tid >> 5;  // 32x8
#pragma unroll
        for (int i = 0; i < 32; i += 8)
            t[ty + i][tx] = W1[(size_t)(k0 + ty + i) * NU + u0 + tx];
        __syncthreads();
#pragma unroll
        for (int i = 0; i < 32; i += 8) {
            float v = t[tx][ty + i];
            g_w1t[(size_t)(u0 + ty + i) * DE + k0 + tx] = __float2half_rn(v);
        }
    } else if (bx < PREP_SHORT) {
        // dec_proj (exact fp32)
        int b3x = bx - PREP_W1_BLOCKS;
        int b = b3x >> 2;
        int u = (b3x & 3) * 256 + tid;
        const float* hd = hdec + b * DE;
        float acc = b1[u];
#pragma unroll 8
        for (int k = 0; k < DE; k++)
            acc = fmaf(hd[k], W1[(size_t)(DE + k) * NU + u], acc);
        g_dp[b * NU + u] = acc;
    } else {
        // henc fp32 -> fp16, one float4 per thread (R12-proven: warp-count parallelism wins)
        size_t i = (size_t)(bx - PREP_SHORT) * 256 + tid;
        float4 v = ((const float4*)henc)[i];
        __half2 h0 = __floats2half2_rn(v.x, v.y);
        __half2 h1 = __floats2half2_rn(v.z, v.w);
        ((uint2*)g_ah)[i] = make_uint2(*(uint32_t*)&h0, *(uint32_t*)&h1);
    }
}

// ---------------- Kernel 2: fp16 mma fused energies — R8-proven, unchanged --------------------
#define STG_BYTES 32768
#define SM_DP (3 * STG_BYTES)          // 98304
#define SM_W2 (SM_DP + 4096)
#define SM_EBUF (SM_W2 + 4096)
#define SM_TOTAL (SM_EBUF + 2048)      // 108544

#define NSTG 128

__global__ __launch_bounds__(256, 2) void k_energies_mma(const float* __restrict__ W2,
                                                         const float* __restrict__ b2) {
    extern __shared__ char smem[];
    uint32_t sbase = smem_u32(smem);
    int tid = threadIdx.x, lane = tid & 31, wid = tid >> 5;
    int mwarp = wid >> 2, nwarp = wid & 3;  // 2 x 4
    int sblk = blockIdx.x, b = blockIdx.y;
    size_t rowbase = (size_t)b * NS + (size_t)sblk * 128;

    float* dp_s = (float*)(smem + SM_DP);
    float* w2_s = (float*)(smem + SM_W2);
    float* e2buf = (float*)(smem + SM_EBUF);
    for (int i = tid; i < NU; i += 256) {
        dp_s[i] = g_dp[b * NU + i];
        w2_s[i] = W2[i];
    }
    for (int i = tid; i < 512; i += 256) e2buf[i] = 0.f;
    __syncthreads();

    uint32_t a_off[4], b_off[2];
#pragma unroll
    for (int mf = 0; mf < 4; mf++) {
        int r = mwarp * 64 + mf * 16 + (lane & 15);
        int kb = (lane >> 4) * 16;
        a_off[mf] = SWZ((uint32_t)(r * 128 + kb));
    }
#pragma unroll
    for (int nf2 = 0; nf2 < 2; nf2++) {
        int n = nwarp * 32 + nf2 * 16 + ((lane >> 4) & 1) * 8 + (lane & 7);
        int kb = ((lane >> 3) & 1) * 16;
        b_off[nf2] = SWZ((uint32_t)(n * 128 + kb));
    }

    auto issue = [&](int fst) {
        int k0 = (fst & 15) << 6;
        int u0 = (fst >> 4) << 7;
        uint32_t sA = sbase + (uint32_t)(fst % 3) * STG_BYTES;
        uint32_t sB = sA + 16384;
#pragma unroll
        for (int i = 0; i < 4; i++) {
            int idx = i * 256 + tid;
            int r = idx >> 3, kc = idx & 7;
            cpa16(sA + SWZ((uint32_t)(r * 128 + kc * 16)),
                  g_ah + (rowbase + r) * DE + k0 + kc * 8);
        }
#pragma unroll
        for (int i = 0; i < 4; i++) {
            int idx = i * 256 + tid;
            int r = idx >> 3, kc = idx & 7;
            cpa16(sB + SWZ((uint32_t)(r * 128 + kc * 16)),
                  g_w1t + (size_t)(u0 + r) * DE + k0 + kc * 8);
        }
        asm volatile("cp.async.commit_group;" ::: "memory");
    };

    float acc[4][4][4];
#pragma unroll
    for (int mf = 0; mf < 4; mf++)
#pragma unroll
        for (int nf = 0; nf < 4; nf++)
#pragma unroll
            for (int j = 0; j < 4; j++) acc[mf][nf][j] = 0.f;

    issue(0);
    issue(1);
    for (int fst = 0; fst < NSTG; fst++) {
        if (fst + 1 < NSTG)
            asm volatile("cp.async.wait_group 1;" ::: "memory");
        else
            asm volatile("cp.async.wait_group 0;" ::: "memory");
        __syncthreads();

        uint32_t abase = sbase + (uint32_t)(fst % 3) * STG_BYTES;
        uint32_t bbase = abase + 16384;
#pragma unroll
        for (int kk = 0; kk < 4; kk++) {
            uint32_t a[4][4], bq[2][4];
#pragma unroll
            for (int mf = 0; mf < 4; mf++) ldsm4(a[mf], abase + (a_off[mf] ^ (kk << 5)));
#pragma unroll
            for (int nf2 = 0; nf2 < 2; nf2++) ldsm4(bq[nf2], bbase + (b_off[nf2] ^ (kk << 5)));
#pragma unroll
            for (int mf = 0; mf < 4; mf++)
#pragma unroll
                for (int nf = 0; nf < 4; nf++) {
                    int nf2 = nf >> 1, h = (nf & 1) * 2;
                    mma16816(acc[mf][nf], a[mf], bq[nf2][h], bq[nf2][h + 1]);
                }
        }
        if (fst + 2 < NSTG) issue(fst + 2);

        if ((fst & 15) == 15) {
            int u0 = (fst >> 4) << 7;
            float rowsum[4][2];
#pragma unroll
            for (int mf = 0; mf < 4; mf++) {
                rowsum[mf][0] = 0.f;
                rowsum[mf][1] = 0.f;
            }
#pragma unroll
            for (int mf = 0; mf < 4; mf++)
#pragma unroll
                for (int nf = 0; nf < 4; nf++)
#pragma unroll
                    for (int j = 0; j < 4; j++) {
                        int u = u0 + nwarp * 32 + nf * 8 + (lane & 3) * 2 + (j & 1);
                        float e1 = acc[mf][nf][j] + dp_s[u];
                        rowsum[mf][j >> 1] = fmaf(tanh_fast(e1), w2_s[u], rowsum[mf][j >> 1]);
                        acc[mf][nf][j] = 0.f;
                    }
#pragma unroll
            for (int mf = 0; mf < 4; mf++)
#pragma unroll
                for (int hh = 0; hh < 2; hh++) {
                    float v = rowsum[mf][hh];
                    v += __shfl_xor_sync(0xffffffffu, v, 1);
                    v += __shfl_xor_sync(0xffffffffu, v, 2);
                    if ((lane & 3) == 0) {
                        int row = mwarp * 64 + mf * 16 + (lane >> 2) + hh * 8;
                        e2buf[nwarp * 128 + row] += v;
                    }
                }
        }
    }
    __syncthreads();
    if (tid < 128) {
        float v = e2buf[tid] + e2buf[128 + tid] + e2buf[256 + tid] + e2buf[384 + tid] + b2[0];
        g_e2[b * NS + sblk * 128 + tid] = fmaxf(v, 0.f);
    }
}

// ---------------- Kernel 4: softmax + context partial + last-block reduce -----------------------
__global__ void k_ctxsoft(float* __restrict__ attn, float* __restrict__ ctx) {
    int sc = blockIdx.x, b = blockIdx.y, t = threadIdx.x;
    __shared__ float red[256];
    __shared__ float w[128];
    __shared__ int amLast;

    // --- softmax reduction (identical algorithm/order to the old k_softmax) ---
    float v[8];
    float mx = -1e30f;
#pragma unroll
    for (int q = 0; q < 8; q++) {
        v[q] = g_e2[b * NS + t + 256 * q];
        mx = fmaxf(mx, v[q]);
    }
    red[t] = mx;
    __syncthreads();
    for (int o = 128; o > 0; o >>= 1) {
        if (t < o) red[t] = fmaxf(red[t], red[t + o]);
        __syncthreads();
    }
    mx = red[0];
    __syncthreads();
    float s = 0.f;
#pragma unroll
    for (int q = 0; q < 8; q++) s += expf(v[q] - mx);
    red[t] = s;
    __syncthreads();
    for (int o = 128; o > 0; o >>= 1) {
        if (t < o) red[t] += red[t + o];
        __syncthreads();
    }
    float inv = 1.f / red[0];
    __syncthreads();

    if (t < 128) {
        float wv = expf(g_e2[b * NS + sc * 128 + t] - mx) * inv;
        w[t] = wv;
        attn[b * NS + sc * 128 + t] = wv;
    }
    __syncthreads();

    // --- context partial (fp16 henc); unroll 8 = more loads in flight, same sequential
    //     accumulator chain -> bit-identical FP order ---
    int d = t * 4;
    float4 acc = make_float4(0.f, 0.f, 0.f, 0.f);
    const __half* hp = g_ah + ((size_t)b * NS + (size_t)sc * 128) * DE + d;
#pragma unroll 8
    for (int s2 = 0; s2 < 128; s2++) {
        float ww = w[s2];
        uint2 hv = *(const uint2*)(hp + (size_t)s2 * DE);
        float2 f0 = __half22float2(*(const __half2*)&hv.x);
        float2 f1 = __half22float2(*(const __half2*)&hv.y);
        acc.x = fmaf(ww, f0.x, acc.x);
        acc.y = fmaf(ww, f0.y, acc.y);
        acc.z = fmaf(ww, f1.x, acc.z);
        acc.w = fmaf(ww, f1.y, acc.w);
    }
    *(float4*)&g_cpart[(size_t)(sc * NB + b) * DE + d] = acc;

    // --- last-block reduction: release (writer) AND acquire (reader) fences ---
    __threadfence();  // release: order this block's g_cpart stores before the RMW
    if (t == 0) {
        int old = atomicAdd(&g_ctr[b], 1);
        __threadfence();  // acquire for t0
        amLast = (old == 15);
    }
    __syncthreads();
    if (amLast) {
        __threadfence();  // acquire for t!=0 before reading other blocks' partials
#pragma unroll
        for (int rep = 0; rep < 4; rep++) {
            int dd = rep * 256 + t;
            float sum = 0.f;
#pragma unroll
            for (int scc = 0; scc < 16; scc++) sum += g_cpart[(size_t)(scc * NB + b) * DE + dd];
            ctx[b * DE + dd] = sum;
        }
        if (t == 0) g_ctr[b] = 0;  // reset for next graph replay
    }
}

extern "C" void kernel_launch(void* const* d_in, const int* in_sizes, int n_in,
                              void* d_out, int out_size) {
    const float* henc = (const float*)d_in[0];
    const float* hdec = (const float*)d_in[1];
    const float* W1 = (const float*)d_in[2];
    const float* b1 = (const float*)d_in[3];
    const float* W2 = (const float*)d_in[4];
    const float* b2 = (const float*)d_in[5];
    float* out = (float*)d_out;
    float* ctx = out;             // [32,1024]
    float* attn = out + NB * DE;  // [32,2048,1]

    cudaFuncSetAttribute(k_energies_mma, cudaFuncAttributeMaxDynamicSharedMemorySize, SM_TOTAL);

    k_prep<<<PREP_BLOCKS, 256>>>(henc, W1, hdec, b1);
    k_energies_mma<<<dim3(16, NB), 256, SM_TOTAL>>>(W2, b2);
    k_ctxsoft<<<dim3(16, NB), 256>>>(attn, ctx);
}